// round 1
// baseline (speedup 1.0000x reference)
#include <cuda_runtime.h>
#include <math.h>

#define N_USERS 100000
#define M_ITEMS 50000
#define N_ALL   150000
#define N_EDGES 4800000
#define DIM     64
#define NF4     (DIM / 4)          // 16 float4 per row
#define TOT_F4  (N_ALL * NF4)      // 2,400,000

// Scratch (static __device__ arrays are allowed; no runtime allocation)
__device__ float4 g_E0[TOT_F4];
__device__ float4 g_E1[TOT_F4];
__device__ float4 g_E2[TOT_F4];
__device__ float4 g_E3[TOT_F4];

// ---------------------------------------------------------------------------
// Build unified embedding E0 = concat(user_emb, item_emb)
// ---------------------------------------------------------------------------
__global__ void concat_kernel(const float4* __restrict__ u,
                              const float4* __restrict__ it) {
    int i = blockIdx.x * blockDim.x + threadIdx.x;
    if (i >= TOT_F4) return;
    const int NU = N_USERS * NF4;   // 1,600,000
    g_E0[i] = (i < NU) ? u[i] : it[i - NU];
}

// dst = c * src  (c = 0 gives the zero-init for the first spmm target)
__global__ void scale_init_kernel(float4* __restrict__ dst,
                                  const float4* __restrict__ src,
                                  float c) {
    int i = blockIdx.x * blockDim.x + threadIdx.x;
    if (i >= TOT_F4) return;
    float4 s = src[i];
    dst[i] = make_float4(c * s.x, c * s.y, c * s.z, c * s.w);
}

// ---------------------------------------------------------------------------
// SpMM: dst[rows[e]] += scale * vals[e] * src[cols[e]]
// 16 threads per edge, one float4 (4 dims) per thread.
// Vector atomicAdd(float4*) -> RED.E.ADD.V4.F32 at L2 (sm_90+).
// ---------------------------------------------------------------------------
__global__ void spmm_kernel(const int*   __restrict__ rows,
                            const int*   __restrict__ cols,
                            const float* __restrict__ vals,
                            const float4* __restrict__ src,
                            float4*       __restrict__ dst,
                            float scale) {
    unsigned int tid = blockIdx.x * blockDim.x + threadIdx.x;
    unsigned int e = tid >> 4;
    unsigned int j = tid & 15u;
    if (e >= N_EDGES) return;
    int r = __ldg(rows + e);
    int c = __ldg(cols + e);
    float v = __ldg(vals + e) * scale;
    float4 x = __ldg(src + (unsigned int)c * NF4 + j);
    float4 y = make_float4(v * x.x, v * x.y, v * x.z, v * x.w);
    atomicAdd(dst + (unsigned int)r * NF4 + j, y);
}

// ---------------------------------------------------------------------------
// Epilogue: band_stop = mean(E0..E3), band_pass = tanh(0.1*E0 - band_stop)
// out row layout: [band_stop(64) | band_pass(64)]  -> 32 float4 per row
// ---------------------------------------------------------------------------
__global__ void final_kernel(float4* __restrict__ out) {
    int i = blockIdx.x * blockDim.x + threadIdx.x;
    if (i >= TOT_F4) return;
    float4 a = g_E0[i];
    float4 b = g_E1[i];
    float4 c = g_E2[i];
    float4 d = g_E3[i];
    float4 bs, bp;
    bs.x = 0.25f * (a.x + b.x + c.x + d.x);
    bs.y = 0.25f * (a.y + b.y + c.y + d.y);
    bs.z = 0.25f * (a.z + b.z + c.z + d.z);
    bs.w = 0.25f * (a.w + b.w + c.w + d.w);
    bp.x = tanhf(0.1f * a.x - bs.x);
    bp.y = tanhf(0.1f * a.y - bs.y);
    bp.z = tanhf(0.1f * a.z - bs.z);
    bp.w = tanhf(0.1f * a.w - bs.w);
    int r = i >> 4;       // row
    int j = i & 15;       // float4 chunk within row
    out[r * 32 + j]      = bs;
    out[r * 32 + 16 + j] = bp;
}

// ---------------------------------------------------------------------------
extern "C" void kernel_launch(void* const* d_in, const int* in_sizes, int n_in,
                              void* d_out, int out_size) {
    const float4* u    = (const float4*)d_in[0];   // user_emb  [100000,64]
    const float4* it   = (const float4*)d_in[1];   // item_emb  [50000,64]
    const int*    rows = (const int*)  d_in[2];    // [4.8M]
    const int*    cols = (const int*)  d_in[3];    // [4.8M]
    const float*  vals = (const float*)d_in[4];    // [4.8M]
    float4* out = (float4*)d_out;                  // [150000,128] f32

    float4 *E0, *E1, *E2, *E3;
    cudaGetSymbolAddress((void**)&E0, g_E0);
    cudaGetSymbolAddress((void**)&E1, g_E1);
    cudaGetSymbolAddress((void**)&E2, g_E2);
    cudaGetSymbolAddress((void**)&E3, g_E3);

    const int TPB = 256;
    const int ELEM_BLKS = (TOT_F4 + TPB - 1) / TPB;                 // 9375
    const unsigned int SPMM_THREADS = (unsigned int)N_EDGES * 16u;  // 76.8M
    const int SPMM_BLKS = (int)((SPMM_THREADS + TPB - 1) / TPB);    // 300000

    // Jacobi(1,1) coefficients
    const float TH1_2 = 1.875f;          // (2k+2)(2k+1)/((k+2)*2k), k=2
    const float TH3_2 = 0.75f;           // (k+1)/(k+2),             k=2
    const float TH1_3 = 56.0f / 30.0f;   // k=3
    const float TH3_3 = 0.8f;            // k=3

    // E0 = concat(user, item)
    concat_kernel<<<ELEM_BLKS, TPB>>>(u, it);

    // e1 = spmm(e0)            (A=B=1 -> (A-B)/2 = 0, (A+B)/2 = 1)
    scale_init_kernel<<<ELEM_BLKS, TPB>>>(E1, E0, 0.0f);
    spmm_kernel<<<SPMM_BLKS, TPB>>>(rows, cols, vals, E0, E1, 1.0f);

    // e2 = th1*spmm(e1) - th3*e0   (theta2 term is 0 since A^2==B^2)
    scale_init_kernel<<<ELEM_BLKS, TPB>>>(E2, E0, -TH3_2);
    spmm_kernel<<<SPMM_BLKS, TPB>>>(rows, cols, vals, E1, E2, TH1_2);

    // e3 = th1*spmm(e2) - th3*e1
    scale_init_kernel<<<ELEM_BLKS, TPB>>>(E3, E1, -TH3_3);
    spmm_kernel<<<SPMM_BLKS, TPB>>>(rows, cols, vals, E2, E3, TH1_3);

    // band_stop / band_pass -> out
    final_kernel<<<ELEM_BLKS, TPB>>>(out);
}

// round 3
// speedup vs baseline: 2.0262x; 2.0262x over previous
#include <cuda_runtime.h>
#include <math.h>

#define N_USERS 100000
#define M_ITEMS 50000
#define N_ALL   150000
#define N_EDGES 4800000
#define DIM     64
#define NF2     (DIM / 2)           // 32 float2 per row
#define NF4     (DIM / 4)           // 16 float4 per row
#define TOT_F2  (N_ALL * NF2)
#define TOT_F4  (N_ALL * NF4)

#define SCAN_BLK 1024
#define N_SCAN_BLOCKS ((N_ALL + SCAN_BLK - 1) / SCAN_BLK)   // 147

// ---- scratch (static device globals; no runtime allocation) ----
__device__ int    g_cnt[N_ALL];
__device__ int    g_off[N_ALL + 1];
__device__ int    g_cur[N_ALL];
__device__ int    g_bsums[256];
__device__ int2   g_edges[N_EDGES];        // packed (col, val-as-int)
__device__ float2 g_E0[TOT_F2];
__device__ float2 g_E1[TOT_F2];
__device__ float2 g_E2[TOT_F2];

// ---------------------------------------------------------------------------
// E0 = concat(user_emb, item_emb); also zero the row-degree counters
// ---------------------------------------------------------------------------
__global__ void concat_zero_kernel(const float4* __restrict__ u,
                                   const float4* __restrict__ it) {
    int i = blockIdx.x * blockDim.x + threadIdx.x;
    if (i < N_ALL) g_cnt[i] = 0;
    if (i >= TOT_F4) return;
    const int NU = N_USERS * NF4;
    float4 v = (i < NU) ? u[i] : it[i - NU];
    ((float4*)g_E0)[i] = v;
}

// ---------------------------------------------------------------------------
// CSR build: histogram -> 2-level exclusive scan -> scatter
// ---------------------------------------------------------------------------
__global__ void hist_kernel(const int* __restrict__ rows) {
    int e = blockIdx.x * blockDim.x + threadIdx.x;
    if (e >= N_EDGES) return;
    atomicAdd(&g_cnt[rows[e]], 1);
}

__global__ void scan1_kernel() {
    __shared__ int sh[SCAN_BLK];
    int t = threadIdx.x;
    int g = blockIdx.x * SCAN_BLK + t;
    int v = (g < N_ALL) ? g_cnt[g] : 0;
    sh[t] = v;
    __syncthreads();
    #pragma unroll
    for (int d = 1; d < SCAN_BLK; d <<= 1) {
        int add = (t >= d) ? sh[t - d] : 0;
        __syncthreads();
        sh[t] += add;
        __syncthreads();
    }
    if (g < N_ALL) g_off[g] = sh[t] - v;           // exclusive within block
    if (t == SCAN_BLK - 1) g_bsums[blockIdx.x] = sh[t];
}

__global__ void scan2_kernel() {                    // 1 block, 256 threads
    __shared__ int sh[256];
    int t = threadIdx.x;
    int v = (t < N_SCAN_BLOCKS) ? g_bsums[t] : 0;
    sh[t] = v;
    __syncthreads();
    #pragma unroll
    for (int d = 1; d < 256; d <<= 1) {
        int add = (t >= d) ? sh[t - d] : 0;
        __syncthreads();
        sh[t] += add;
        __syncthreads();
    }
    g_bsums[t] = sh[t] - v;                         // exclusive block offsets
}

__global__ void add_off_kernel() {
    int g = blockIdx.x * blockDim.x + threadIdx.x;
    if (g >= N_ALL) return;
    int o = g_off[g] + g_bsums[g / SCAN_BLK];
    g_off[g] = o;
    g_cur[g] = o;
    if (g == 0) g_off[N_ALL] = N_EDGES;
}

__global__ void scatter_kernel(const int*   __restrict__ rows,
                               const int*   __restrict__ cols,
                               const float* __restrict__ vals) {
    int e = blockIdx.x * blockDim.x + threadIdx.x;
    if (e >= N_EDGES) return;
    int p = atomicAdd(&g_cur[rows[e]], 1);
    g_edges[p] = make_int2(cols[e], __float_as_int(vals[e]));
}

// ---------------------------------------------------------------------------
// Warp-per-row CSR SpMM:  dst[r] = th1 * sum_e v_e*src[c_e]  -  th3 * prev[r]
// lane handles 2 dims (float2); per edge: 8B broadcast + 256B coalesced gather.
// 4-deep pipelining: 4 independent gathers in flight to cover L2 latency.
// ---------------------------------------------------------------------------
__device__ __forceinline__ void spmm_row_acc(const float2* __restrict__ src,
                                             int s, int e, int lane,
                                             float2& acc) {
    float2 a0 = make_float2(0.f, 0.f);
    float2 a1 = make_float2(0.f, 0.f);
    float2 a2 = make_float2(0.f, 0.f);
    float2 a3 = make_float2(0.f, 0.f);
    int i = s;
    for (; i + 3 < e; i += 4) {
        int2 cv0 = __ldg(&g_edges[i]);
        int2 cv1 = __ldg(&g_edges[i + 1]);
        int2 cv2 = __ldg(&g_edges[i + 2]);
        int2 cv3 = __ldg(&g_edges[i + 3]);
        float2 x0 = __ldg(src + (unsigned)cv0.x * NF2 + lane);
        float2 x1 = __ldg(src + (unsigned)cv1.x * NF2 + lane);
        float2 x2 = __ldg(src + (unsigned)cv2.x * NF2 + lane);
        float2 x3 = __ldg(src + (unsigned)cv3.x * NF2 + lane);
        float v0 = __int_as_float(cv0.y);
        float v1 = __int_as_float(cv1.y);
        float v2 = __int_as_float(cv2.y);
        float v3 = __int_as_float(cv3.y);
        a0.x += v0 * x0.x; a0.y += v0 * x0.y;
        a1.x += v1 * x1.x; a1.y += v1 * x1.y;
        a2.x += v2 * x2.x; a2.y += v2 * x2.y;
        a3.x += v3 * x3.x; a3.y += v3 * x3.y;
    }
    for (; i < e; i++) {
        int2 cv = __ldg(&g_edges[i]);
        float2 x = __ldg(src + (unsigned)cv.x * NF2 + lane);
        float v = __int_as_float(cv.y);
        a0.x += v * x.x; a0.y += v * x.y;
    }
    acc.x = (a0.x + a1.x) + (a2.x + a3.x);
    acc.y = (a0.y + a1.y) + (a2.y + a3.y);
}

__global__ __launch_bounds__(256)
void spmm_csr_kernel(const float2* __restrict__ src,
                     const float2* __restrict__ prev,
                     float2*       __restrict__ dst,
                     float th1, float th3) {
    int w    = (blockIdx.x * blockDim.x + threadIdx.x) >> 5;
    int lane = threadIdx.x & 31;
    if (w >= N_ALL) return;
    int s = __ldg(&g_off[w]);
    int e = __ldg(&g_off[w + 1]);
    float2 acc;
    spmm_row_acc(src, s, e, lane, acc);
    float2 p = __ldg(prev + w * NF2 + lane);
    dst[w * NF2 + lane] = make_float2(th1 * acc.x - th3 * p.x,
                                      th1 * acc.y - th3 * p.y);
}

// Last pass: compute e3 row on the fly and fuse the band_stop/band_pass epilogue
__global__ __launch_bounds__(256)
void spmm_final_kernel(float2* __restrict__ out, float th1, float th3) {
    int w    = (blockIdx.x * blockDim.x + threadIdx.x) >> 5;
    int lane = threadIdx.x & 31;
    if (w >= N_ALL) return;
    int s = __ldg(&g_off[w]);
    int e = __ldg(&g_off[w + 1]);
    float2 acc;
    spmm_row_acc(g_E2, s, e, lane, acc);

    float2 e0 = __ldg(g_E0 + w * NF2 + lane);
    float2 e1 = __ldg(g_E1 + w * NF2 + lane);
    float2 e2 = __ldg(g_E2 + w * NF2 + lane);
    float2 e3 = make_float2(th1 * acc.x - th3 * e1.x,
                            th1 * acc.y - th3 * e1.y);
    float2 bs = make_float2(0.25f * (e0.x + e1.x + e2.x + e3.x),
                            0.25f * (e0.y + e1.y + e2.y + e3.y));
    float2 bp = make_float2(tanhf(0.1f * e0.x - bs.x),
                            tanhf(0.1f * e0.y - bs.y));
    // out row = 128 floats = 64 float2: [band_stop | band_pass]
    out[w * 64 + lane]      = bs;
    out[w * 64 + 32 + lane] = bp;
}

// ---------------------------------------------------------------------------
extern "C" void kernel_launch(void* const* d_in, const int* in_sizes, int n_in,
                              void* d_out, int out_size) {
    const float4* u    = (const float4*)d_in[0];
    const float4* it   = (const float4*)d_in[1];
    const int*    rows = (const int*)  d_in[2];
    const int*    cols = (const int*)  d_in[3];
    const float*  vals = (const float*)d_in[4];
    float2* out = (float2*)d_out;

    float2 *E0, *E1, *E2;
    cudaGetSymbolAddress((void**)&E0, g_E0);
    cudaGetSymbolAddress((void**)&E1, g_E1);
    cudaGetSymbolAddress((void**)&E2, g_E2);

    const int TPB = 256;
    const int ELEM_BLKS = (TOT_F4 + TPB - 1) / TPB;
    const int EDGE_BLKS = (N_EDGES + TPB - 1) / TPB;
    const int NODE_BLKS = (N_ALL + TPB - 1) / TPB;
    const int SPMM_BLKS = (N_ALL * 32 + TPB - 1) / TPB;   // warp per row

    // Jacobi(1,1) coefficients
    const float TH1_2 = 1.875f;
    const float TH3_2 = 0.75f;
    const float TH1_3 = 56.0f / 30.0f;
    const float TH3_3 = 0.8f;

    // E0 = concat, counters = 0
    concat_zero_kernel<<<ELEM_BLKS, TPB>>>(u, it);

    // CSR build
    hist_kernel<<<EDGE_BLKS, TPB>>>(rows);
    scan1_kernel<<<N_SCAN_BLOCKS, SCAN_BLK>>>();
    scan2_kernel<<<1, 256>>>();
    add_off_kernel<<<NODE_BLKS, TPB>>>();
    scatter_kernel<<<EDGE_BLKS, TPB>>>(rows, cols, vals);

    // e1 = spmm(e0)
    spmm_csr_kernel<<<SPMM_BLKS, TPB>>>(E0, E0, E1, 1.0f, 0.0f);
    // e2 = th1*spmm(e1) - th3*e0
    spmm_csr_kernel<<<SPMM_BLKS, TPB>>>(E1, E0, E2, TH1_2, TH3_2);
    // e3 = th1*spmm(e2) - th3*e1, fused with band_stop/band_pass epilogue
    spmm_final_kernel<<<SPMM_BLKS, TPB>>>(out, TH1_3, TH3_3);
}

// round 4
// speedup vs baseline: 2.1477x; 1.0600x over previous
#include <cuda_runtime.h>
#include <cuda_fp16.h>
#include <math.h>

#define N_USERS 100000
#define M_ITEMS 50000
#define N_ALL   150000
#define N_EDGES 4800000
#define DIM     64
#define NF2     (DIM / 2)           // 32 float2 per row (also 32 half2 per row)
#define NF4     (DIM / 4)
#define TOT_F2  (N_ALL * NF2)
#define TOT_F4  (N_ALL * NF4)

#define SCAN_BLK 1024
#define N_SCAN_BLOCKS ((N_ALL + SCAN_BLK - 1) / SCAN_BLK)   // 147

// ---- scratch (static device globals; no runtime allocation) ----
__device__ int     g_cnt[N_ALL];
__device__ int     g_off[N_ALL + 1];
__device__ int     g_cur[N_ALL];
__device__ int     g_bsums[256];
__device__ int2    g_edges[N_EDGES];       // packed (col, val-as-int)
__device__ float2  g_E0[TOT_F2];           // fp32 levels (exact recurrence)
__device__ float2  g_E1[TOT_F2];
__device__ float2  g_E2[TOT_F2];
__device__ __half2 g_H0[TOT_F2];           // fp16 shadows (gather sources)
__device__ __half2 g_H1[TOT_F2];
__device__ __half2 g_H2[TOT_F2];

// ---------------------------------------------------------------------------
// E0 = concat(user_emb, item_emb) in fp32 + fp16 shadow; zero degree counters
// ---------------------------------------------------------------------------
__global__ void concat_zero_kernel(const float4* __restrict__ u,
                                   const float4* __restrict__ it) {
    int i = blockIdx.x * blockDim.x + threadIdx.x;
    if (i < N_ALL) g_cnt[i] = 0;
    if (i >= TOT_F4) return;
    const int NU = N_USERS * NF4;
    float4 v = (i < NU) ? u[i] : it[i - NU];
    ((float4*)g_E0)[i] = v;
    g_H0[2 * i]     = __floats2half2_rn(v.x, v.y);
    g_H0[2 * i + 1] = __floats2half2_rn(v.z, v.w);
}

// ---------------------------------------------------------------------------
// CSR build: histogram -> 2-level exclusive scan -> scatter
// ---------------------------------------------------------------------------
__global__ void hist_kernel(const int* __restrict__ rows) {
    int e = blockIdx.x * blockDim.x + threadIdx.x;
    if (e >= N_EDGES) return;
    atomicAdd(&g_cnt[rows[e]], 1);
}

__global__ void scan1_kernel() {
    __shared__ int sh[SCAN_BLK];
    int t = threadIdx.x;
    int g = blockIdx.x * SCAN_BLK + t;
    int v = (g < N_ALL) ? g_cnt[g] : 0;
    sh[t] = v;
    __syncthreads();
    #pragma unroll
    for (int d = 1; d < SCAN_BLK; d <<= 1) {
        int add = (t >= d) ? sh[t - d] : 0;
        __syncthreads();
        sh[t] += add;
        __syncthreads();
    }
    if (g < N_ALL) g_off[g] = sh[t] - v;           // exclusive within block
    if (t == SCAN_BLK - 1) g_bsums[blockIdx.x] = sh[t];
}

__global__ void scan2_kernel() {                    // 1 block, 256 threads
    __shared__ int sh[256];
    int t = threadIdx.x;
    int v = (t < N_SCAN_BLOCKS) ? g_bsums[t] : 0;
    sh[t] = v;
    __syncthreads();
    #pragma unroll
    for (int d = 1; d < 256; d <<= 1) {
        int add = (t >= d) ? sh[t - d] : 0;
        __syncthreads();
        sh[t] += add;
        __syncthreads();
    }
    g_bsums[t] = sh[t] - v;                         // exclusive block offsets
}

__global__ void add_off_kernel() {
    int g = blockIdx.x * blockDim.x + threadIdx.x;
    if (g >= N_ALL) return;
    int o = g_off[g] + g_bsums[g / SCAN_BLK];
    g_off[g] = o;
    g_cur[g] = o;
    if (g == 0) g_off[N_ALL] = N_EDGES;
}

__global__ void scatter_kernel(const int*   __restrict__ rows,
                               const int*   __restrict__ cols,
                               const float* __restrict__ vals) {
    int e = blockIdx.x * blockDim.x + threadIdx.x;
    if (e >= N_EDGES) return;
    int p = atomicAdd(&g_cur[rows[e]], 1);
    g_edges[p] = make_int2(cols[e], __float_as_int(vals[e]));
}

// ---------------------------------------------------------------------------
// Warp-per-row CSR SpMM over the fp16 shadow, fp32 accumulation.
// lane handles 2 dims (half2 = 4B); per edge: 8B broadcast + 128B gather.
// 4-deep pipelining: 4 independent gathers in flight to cover L2 latency.
// ---------------------------------------------------------------------------
__device__ __forceinline__ void spmm_row_acc(const __half2* __restrict__ src,
                                             int s, int e, int lane,
                                             float2& acc) {
    float2 a0 = make_float2(0.f, 0.f);
    float2 a1 = make_float2(0.f, 0.f);
    float2 a2 = make_float2(0.f, 0.f);
    float2 a3 = make_float2(0.f, 0.f);
    int i = s;
    for (; i + 3 < e; i += 4) {
        int2 cv0 = __ldg(&g_edges[i]);
        int2 cv1 = __ldg(&g_edges[i + 1]);
        int2 cv2 = __ldg(&g_edges[i + 2]);
        int2 cv3 = __ldg(&g_edges[i + 3]);
        float2 x0 = __half22float2(__ldg(src + (unsigned)cv0.x * NF2 + lane));
        float2 x1 = __half22float2(__ldg(src + (unsigned)cv1.x * NF2 + lane));
        float2 x2 = __half22float2(__ldg(src + (unsigned)cv2.x * NF2 + lane));
        float2 x3 = __half22float2(__ldg(src + (unsigned)cv3.x * NF2 + lane));
        float v0 = __int_as_float(cv0.y);
        float v1 = __int_as_float(cv1.y);
        float v2 = __int_as_float(cv2.y);
        float v3 = __int_as_float(cv3.y);
        a0.x += v0 * x0.x; a0.y += v0 * x0.y;
        a1.x += v1 * x1.x; a1.y += v1 * x1.y;
        a2.x += v2 * x2.x; a2.y += v2 * x2.y;
        a3.x += v3 * x3.x; a3.y += v3 * x3.y;
    }
    for (; i < e; i++) {
        int2 cv = __ldg(&g_edges[i]);
        float2 x = __half22float2(__ldg(src + (unsigned)cv.x * NF2 + lane));
        float v = __int_as_float(cv.y);
        a0.x += v * x.x; a0.y += v * x.y;
    }
    acc.x = (a0.x + a1.x) + (a2.x + a3.x);
    acc.y = (a0.y + a1.y) + (a2.y + a3.y);
}

// dst = th1*spmm(srcH) - th3*prev  (fp32), plus fp16 shadow of dst
__global__ __launch_bounds__(256)
void spmm_csr_kernel(const __half2* __restrict__ srcH,
                     const float2*  __restrict__ prev,
                     float2*        __restrict__ dst,
                     __half2*       __restrict__ dstH,
                     float th1, float th3) {
    int w    = (blockIdx.x * blockDim.x + threadIdx.x) >> 5;
    int lane = threadIdx.x & 31;
    if (w >= N_ALL) return;
    int s = __ldg(&g_off[w]);
    int e = __ldg(&g_off[w + 1]);
    float2 acc;
    spmm_row_acc(srcH, s, e, lane, acc);
    float2 p = __ldg(prev + w * NF2 + lane);
    float2 r = make_float2(th1 * acc.x - th3 * p.x,
                           th1 * acc.y - th3 * p.y);
    dst[w * NF2 + lane]  = r;
    dstH[w * NF2 + lane] = __floats2half2_rn(r.x, r.y);
}

// Last pass: e3 on the fly, fused band_stop/band_pass epilogue
__global__ __launch_bounds__(256)
void spmm_final_kernel(float2* __restrict__ out, float th1, float th3) {
    int w    = (blockIdx.x * blockDim.x + threadIdx.x) >> 5;
    int lane = threadIdx.x & 31;
    if (w >= N_ALL) return;
    int s = __ldg(&g_off[w]);
    int e = __ldg(&g_off[w + 1]);
    float2 acc;
    spmm_row_acc(g_H2, s, e, lane, acc);

    float2 e0 = __ldg(g_E0 + w * NF2 + lane);
    float2 e1 = __ldg(g_E1 + w * NF2 + lane);
    float2 e2 = __ldg(g_E2 + w * NF2 + lane);
    float2 e3 = make_float2(th1 * acc.x - th3 * e1.x,
                            th1 * acc.y - th3 * e1.y);
    float2 bs = make_float2(0.25f * (e0.x + e1.x + e2.x + e3.x),
                            0.25f * (e0.y + e1.y + e2.y + e3.y));
    float2 bp = make_float2(tanhf(0.1f * e0.x - bs.x),
                            tanhf(0.1f * e0.y - bs.y));
    out[w * 64 + lane]      = bs;
    out[w * 64 + 32 + lane] = bp;
}

// ---------------------------------------------------------------------------
extern "C" void kernel_launch(void* const* d_in, const int* in_sizes, int n_in,
                              void* d_out, int out_size) {
    const float4* u    = (const float4*)d_in[0];
    const float4* it   = (const float4*)d_in[1];
    const int*    rows = (const int*)  d_in[2];
    const int*    cols = (const int*)  d_in[3];
    const float*  vals = (const float*)d_in[4];
    float2* out = (float2*)d_out;

    float2 *E0, *E1, *E2;
    __half2 *H0, *H1, *H2;
    cudaGetSymbolAddress((void**)&E0, g_E0);
    cudaGetSymbolAddress((void**)&E1, g_E1);
    cudaGetSymbolAddress((void**)&E2, g_E2);
    cudaGetSymbolAddress((void**)&H0, g_H0);
    cudaGetSymbolAddress((void**)&H1, g_H1);
    cudaGetSymbolAddress((void**)&H2, g_H2);

    const int TPB = 256;
    const int ELEM_BLKS = (TOT_F4 + TPB - 1) / TPB;
    const int EDGE_BLKS = (N_EDGES + TPB - 1) / TPB;
    const int NODE_BLKS = (N_ALL + TPB - 1) / TPB;
    const int SPMM_BLKS = (N_ALL * 32 + TPB - 1) / TPB;   // warp per row

    // Jacobi(1,1) coefficients
    const float TH1_2 = 1.875f;
    const float TH3_2 = 0.75f;
    const float TH1_3 = 56.0f / 30.0f;
    const float TH3_3 = 0.8f;

    // E0/H0 = concat, counters = 0
    concat_zero_kernel<<<ELEM_BLKS, TPB>>>(u, it);

    // CSR build
    hist_kernel<<<EDGE_BLKS, TPB>>>(rows);
    scan1_kernel<<<N_SCAN_BLOCKS, SCAN_BLK>>>();
    scan2_kernel<<<1, 256>>>();
    add_off_kernel<<<NODE_BLKS, TPB>>>();
    scatter_kernel<<<EDGE_BLKS, TPB>>>(rows, cols, vals);

    // e1 = spmm(e0)
    spmm_csr_kernel<<<SPMM_BLKS, TPB>>>(H0, E0, E1, H1, 1.0f, 0.0f);
    // e2 = th1*spmm(e1) - th3*e0
    spmm_csr_kernel<<<SPMM_BLKS, TPB>>>(H1, E0, E2, H2, TH1_2, TH3_2);
    // e3 = th1*spmm(e2) - th3*e1, fused epilogue
    spmm_final_kernel<<<SPMM_BLKS, TPB>>>(out, TH1_3, TH3_3);
}